// round 4
// baseline (speedup 1.0000x reference)
#include <cuda_runtime.h>
#include <cuda_bf16.h>

// Lower-triangular packed index
#define TI(i,j) (((i)*((i)+1))/2 + (j))

#define BATCH 4
#define SEQ   64
#define NBT   (BATCH*SEQ)   // 256
#define NV    2000
#define DIMN  8
// log(2*pi)
#define LOG2PI_F 1.8378770664093453f

// ---------- device scratch (no allocations allowed) ----------
__device__ float  g_lam0[NBT * 36];   // per (b,t): lower-tri of lam0 (= lam2)
__device__ float  g_eta0[NBT * 8];    // per (b,t): eta0 (= eta2)
__device__ float  g_c0[NBT];          // per (b,t): 0.5*(logdet0 - q0) - 4*log(2pi)
__device__ float4 g_vd0[NV], g_vd1[NV];   // per v: diag precision 1/cho^2 (8)
__device__ float4 g_ve0[NV], g_ve1[NV];   // per v: eta1 = mu/cho^2 (8)
__device__ float  g_vc1[NV];              // per v: 0.5*(logdet1 - q1)

// ---------- 8x8 in-register Cholesky (lower-tri packed, fully unrolled) ----------
template<bool LD>
__device__ __forceinline__ void chol8(float* A, float* invd, float& lp1, float& lp2) {
#pragma unroll
    for (int k = 0; k < 8; k++) {
        float p = A[TI(k,k)];
        if (LD) { if (k < 4) lp1 *= p; else lp2 *= p; }
        float r = rsqrtf(p);
        invd[k] = r;
#pragma unroll
        for (int i = k + 1; i < 8; i++) A[TI(i,k)] *= r;
#pragma unroll
        for (int i = k + 1; i < 8; i++) {
#pragma unroll
            for (int j = k + 1; j <= i; j++)
                A[TI(i,j)] = fmaf(-A[TI(i,k)], A[TI(j,k)], A[TI(i,j)]);
        }
    }
}

// ---------- per-vocab precompute ----------
__global__ void vprep_kernel(const float* __restrict__ dmu, const float* __restrict__ dcho) {
    int v = blockIdx.x * blockDim.x + threadIdx.x;
    if (v >= NV) return;
    float d[8], e[8];
    float q1 = 0.f, p1 = 1.f, p2 = 1.f;
#pragma unroll
    for (int i = 0; i < 8; i++) {
        float m = dmu[v * 8 + i];
        float c = dcho[v * 8 + i];
        float di = 1.0f / (c * c);
        d[i] = di;
        e[i] = m * di;
        q1 = fmaf(e[i], m, q1);
        if (i < 4) p1 *= di; else p2 *= di;
    }
    float ld1 = __logf(p1) + __logf(p2);
    g_vd0[v] = make_float4(d[0], d[1], d[2], d[3]);
    g_vd1[v] = make_float4(d[4], d[5], d[6], d[7]);
    g_ve0[v] = make_float4(e[0], e[1], e[2], e[3]);
    g_ve1[v] = make_float4(e[4], e[5], e[6], e[7]);
    g_vc1[v] = 0.5f * (ld1 - q1);
}

// ---------- setup (lam_t, eta_t) + sequential scan, 1 block / 4 warps ----------
__global__ void __launch_bounds__(128) prep_scan_kernel(
    const int*   __restrict__ sent,
    const float* __restrict__ emu,
    const float* __restrict__ echo,
    const float* __restrict__ tmu,
    const float* __restrict__ tcho)
{
    __shared__ float sW[16][16];
    __shared__ float sLam[16][16];
    __shared__ float setat[16];

    int tid = threadIdx.x;

    // W = inv(Tc), Tc lower-triangular. Column j per thread.
    if (tid < 16) {
        int j = tid;
        for (int i = 0; i < 16; i++) {
            if (i < j) { sW[i][j] = 0.f; }
            else {
                float s = (i == j) ? 1.0f : 0.0f;
                for (int k = j; k < i; k++) s = fmaf(-tcho[i * 16 + k], sW[k][j], s);
                sW[i][j] = s / tcho[i * 16 + i];
            }
        }
    }
    __syncthreads();

    // lam_t = W W^T
    for (int e = tid; e < 256; e += 128) {
        int i = e >> 4, j = e & 15;
        int m = i < j ? i : j;
        float s = 0.f;
        for (int k = 0; k <= m; k++) s = fmaf(sW[i][k], sW[j][k], s);
        sLam[i][j] = s;
    }
    __syncthreads();

    // eta_t = lam_t @ mu
    if (tid < 16) {
        float s = 0.f;
        for (int k = 0; k < 16; k++) s = fmaf(sLam[tid][k], tmu[k], s);
        setat[tid] = s;
    }
    __syncthreads();

    // ---- scan: warp w handles batch w ----
    int w = tid >> 5, lane = tid & 31;
    int b = w;

    float lam1[36], eta1[8];   // replicated carry: lam2_prev (= lam1), eta2_prev (= eta1)
#pragma unroll
    for (int i = 0; i < 8; i++) {
        eta1[i] = 0.f;
#pragma unroll
        for (int j = 0; j <= i; j++) lam1[TI(i,j)] = (i == j) ? 1.0f : 0.0f;
    }

    for (int t = 0; t < 64; t++) {
        int tok = sent[b * 64 + t];

        // A = lam_t[0:8,0:8] + lam1 ; Cholesky (replicated across lanes)
        float A[36];
#pragma unroll
        for (int i = 0; i < 8; i++)
#pragma unroll
            for (int j = 0; j <= i; j++)
                A[TI(i,j)] = sLam[i][j] + lam1[TI(i,j)];

        float invd[8];
        float du1, du2;
        chol8<false>(A, invd, du1, du2);

        // 9 RHS forward solve, lane-parallel:
        //   lanes 0..7 : columns of B = lam_t[0:8, 8:16]
        //   lanes 8..31: ea = eta_t[0:8] + eta1  (only lane 8's result is used)
        float rhs[8];
        bool isB = (lane < 8);
#pragma unroll
        for (int i = 0; i < 8; i++)
            rhs[i] = isB ? sLam[i][8 + lane] : (setat[i] + eta1[i]);

        float y[8];
#pragma unroll
        for (int i = 0; i < 8; i++) {
            float s = rhs[i];
#pragma unroll
            for (int j = 0; j < i; j++) s = fmaf(-A[TI(i,j)], y[j], s);
            y[i] = s * invd[i];
        }

        // ss[i] on lane j = (Y^T Y)[i][j]  (lane 8: (Y^T yea)[i])
        float ss[8] = {0.f, 0.f, 0.f, 0.f, 0.f, 0.f, 0.f, 0.f};
#pragma unroll
        for (int k = 0; k < 8; k++) {
            float yk = y[k];
#pragma unroll
            for (int i = 0; i < 8; i++) {
                float yki = __shfl_sync(0xffffffffu, yk, i);
                ss[i] = fmaf(yki, yk, ss[i]);
            }
        }

        // word-level precision / mean
        float lw[8], wm[8];
#pragma unroll
        for (int i = 0; i < 8; i++) {
            float c = echo[tok * 8 + i];
            wm[i] = emu[tok * 8 + i];
            lw[i] = 1.0f / (c * c);
        }

        // lam2 = C - Y^T Y + diag(lw) ; eta2 = eb - Y^T yea + wm*lw   (replicate via shfl)
#pragma unroll
        for (int i = 0; i < 8; i++) {
#pragma unroll
            for (int j = 0; j <= i; j++) {
                float v = __shfl_sync(0xffffffffu, ss[i], j);
                float nv = sLam[8 + i][8 + j] - v;
                if (i == j) nv += lw[i];
                lam1[TI(i,j)] = nv;
            }
            float corr = __shfl_sync(0xffffffffu, ss[i], 8);
            eta1[i] = setat[8 + i] - corr + wm[i] * lw[i];
        }

        if (lane == 0) {
            int bt = b * 64 + t;
            float* ol = &g_lam0[bt * 36];
#pragma unroll
            for (int q = 0; q < 36; q++) ol[q] = lam1[q];
            float* oe = &g_eta0[bt * 8];
#pragma unroll
            for (int i = 0; i < 8; i++) oe[i] = eta1[i];
        }
    }
}

// ---------- per-(b,t) constant c0 ----------
__global__ void c0_kernel() {
    int bt = threadIdx.x;  // 256 threads
    float A[36];
#pragma unroll
    for (int q = 0; q < 36; q++) A[q] = g_lam0[bt * 36 + q];
    float invd[8];
    float p1 = 1.f, p2 = 1.f;
    chol8<true>(A, invd, p1, p2);

    float z[8], q0 = 0.f;
#pragma unroll
    for (int i = 0; i < 8; i++) {
        float s = g_eta0[bt * 8 + i];
#pragma unroll
        for (int j = 0; j < i; j++) s = fmaf(-A[TI(i,j)], z[j], s);
        z[i] = s * invd[i];
        q0 = fmaf(z[i], z[i], q0);
    }
    float ld0 = __logf(p1) + __logf(p2);
    g_c0[bt] = 0.5f * (ld0 - q0) - 4.0f * LOG2PI_F;
}

// ---------- main phase: one thread per (b,t,v) ----------
__global__ void __launch_bounds__(256) main_kernel(float* __restrict__ out) {
    __shared__ float sl[36];
    __shared__ float se[8];
    __shared__ float sc0;

    int bt = blockIdx.y;
    int tid = threadIdx.x;
    if (tid < 36) sl[tid] = g_lam0[bt * 36 + tid];
    else if (tid < 44) se[tid - 36] = g_eta0[bt * 8 + (tid - 36)];
    else if (tid == 44) sc0 = g_c0[bt];
    __syncthreads();

    int v = blockIdx.x * 250 + tid;
    if (tid >= 250) return;

    float4 d0 = g_vd0[v], d1 = g_vd1[v];
    float4 e0 = g_ve0[v], e1 = g_ve1[v];
    float  c1 = g_vc1[v];

    float dd[8] = {d0.x, d0.y, d0.z, d0.w, d1.x, d1.y, d1.z, d1.w};
    float ee[8] = {e0.x, e0.y, e0.z, e0.w, e1.x, e1.y, e1.z, e1.w};

    float A[36];
#pragma unroll
    for (int i = 0; i < 8; i++)
#pragma unroll
        for (int j = 0; j <= i; j++)
            A[TI(i,j)] = sl[TI(i,j)] + ((i == j) ? dd[i] : 0.f);

    float invd[8];
    float p1 = 1.f, p2 = 1.f;
    chol8<true>(A, invd, p1, p2);

    float z[8], p3 = 0.f;
#pragma unroll
    for (int i = 0; i < 8; i++) {
        float s = se[i] + ee[i];
#pragma unroll
        for (int j = 0; j < i; j++) s = fmaf(-A[TI(i,j)], z[j], s);
        z[i] = s * invd[i];
        p3 = fmaf(z[i], z[i], p3);
    }
    float ldn = __logf(p1) + __logf(p2);

    out[bt * NV + v] = sc0 + c1 + 0.5f * (p3 - ldn);
}

// ---------- launch ----------
extern "C" void kernel_launch(void* const* d_in, const int* in_sizes, int n_in,
                              void* d_out, int out_size) {
    const int*   sent = (const int*)  d_in[0];
    // d_in[1] = masks (all ones, unused by reference math)
    const float* emu  = (const float*)d_in[2];
    const float* echo = (const float*)d_in[3];
    const float* tmu  = (const float*)d_in[4];
    const float* tcho = (const float*)d_in[5];
    const float* dmu  = (const float*)d_in[6];
    const float* dcho = (const float*)d_in[7];
    float* out = (float*)d_out;

    vprep_kernel<<<16, 128>>>(dmu, dcho);
    prep_scan_kernel<<<1, 128>>>(sent, emu, echo, tmu, tcho);
    c0_kernel<<<1, 256>>>();
    main_kernel<<<dim3(8, NBT), 256>>>(out);
}